// round 17
// baseline (speedup 1.0000x reference)
#include <cuda_runtime.h>
#include <math.h>
#include <stdint.h>

// ---------------------------------------------------------------------------
// SSITrimLoss: masked scale/shift-invariant trimmed L1 loss.
// Pipeline (5 launches) — R16 structure; level-0 now 4096 bins (shift 20),
// compact sweep ILP-8:
//   1. pack      : moments + compact valid (p,g) pairs (__ldcs, ILP-2)
//   2. finalize  : alpha/beta/k per sample; zero hists/counters/out
//   3. hist      : res=|a*p+b-g| from pairs, 4096-bin count hist (ILP-4)
//   4. compact   : per-block level-0 scan + ONE sweep (ILP-8) of pairs ->
//                  below-bin sum (regs) + staged gather of in-bin candidates
//   5. finish    : 20-bit refine (1024+1024 bins, ILP-4) -> atomicAdd(out)
// Selection is bit-exact (monotone uint encoding of non-negative floats).
// ---------------------------------------------------------------------------

#define BB     32
#define NMAX   491520
#define TPB    256
#define BLKX   32
#define SEGLEN (NMAX / BLKX)
#define FULLM  0xffffffffu
#define HBINS  4096
#define HSHIFT 20
#define CAP    4096         /* staging buffer entries */
#define TILE   (TPB * 8)    /* 2048 elements per tile = 8 per thread */

__device__ __align__(16) float2       g_pair[(size_t)BB * NMAX];
__device__ __align__(16) unsigned int g_cand[(size_t)BB * NMAX];
__device__ float              g_part[BB][BLKX][5];
__device__ int                g_segcnt[BB][BLKX];
__device__ unsigned int       g_hcnt[BB][HBINS];
__device__ float              g_alpha[BB], g_beta[BB];
__device__ int                g_k[BB];
__device__ long long          g_rank[BB];     // k-1 (set by finalize)
__device__ long long          g_rank2[BB];    // rank within selected bin
__device__ int                g_sel0[BB];
__device__ double             g_sumbelow[BB];
__device__ long long          g_cntbelow[BB];
__device__ int                g_candcnt[BB];

// ------------------------- warp reduce/scan helpers ------------------------
__device__ __forceinline__ float warp_sum(float v) {
    #pragma unroll
    for (int off = 16; off; off >>= 1) v += __shfl_down_sync(FULLM, v, off);
    return v;
}
__device__ __forceinline__ double warp_sum_d(double v) {
    #pragma unroll
    for (int off = 16; off; off >>= 1) v += __shfl_down_sync(FULLM, v, off);
    return v;
}
__device__ __forceinline__ long long warp_sum_ll(long long v) {
    #pragma unroll
    for (int off = 16; off; off >>= 1) v += __shfl_down_sync(FULLM, v, off);
    return v;
}
__device__ __forceinline__ int warp_scan_incl(int v, int lane) {
    #pragma unroll
    for (int off = 1; off < 32; off <<= 1) {
        int t = __shfl_up_sync(FULLM, v, off);
        if (lane >= off) v += t;
    }
    return v;
}

// ------------------------ 1. pack (moments + gather) -----------------------
__global__ __launch_bounds__(TPB) void pack_kernel(
        const float* __restrict__ pred, const float* __restrict__ gt,
        const int* __restrict__ mask, int N) {
    int b = blockIdx.y;
    int n4 = N >> 2;
    int chunk4 = n4 / BLKX;
    int start = blockIdx.x * chunk4;
    int end   = (blockIdx.x == BLKX - 1) ? n4 : start + chunk4;

    const float4* p4 = reinterpret_cast<const float4*>(pred) + (size_t)b * n4;
    const float4* g4 = reinterpret_cast<const float4*>(gt)   + (size_t)b * n4;
    const int4*   m4 = reinterpret_cast<const int4*>(mask)   + (size_t)b * n4;
    float2* out = g_pair + (size_t)b * NMAX + (size_t)blockIdx.x * SEGLEN;

    __shared__ int s_cnt;
    if (threadIdx.x == 0) s_cnt = 0;
    __syncthreads();

    int lane = threadIdx.x & 31;
    unsigned lmask = (1u << lane) - 1u;
    float sn = 0.f, sp = 0.f, sg = 0.f, spp = 0.f, spg = 0.f;

    int i = start + threadIdx.x;
    for (; i + TPB < end; i += 2*TPB) {
        float4 pA = __ldcs(&p4[i]);
        float4 gA = __ldcs(&g4[i]);
        int4   mA = __ldcs(&m4[i]);
        float4 pB = __ldcs(&p4[i + TPB]);
        float4 gB = __ldcs(&g4[i + TPB]);
        int4   mB = __ldcs(&m4[i + TPB]);

        bool a0 = mA.x > 0, a1 = mA.y > 0, a2 = mA.z > 0, a3 = mA.w > 0;
        bool b0 = mB.x > 0, b1 = mB.y > 0, b2 = mB.z > 0, b3 = mB.w > 0;
        if (a0) { sn += 1.f; sp += pA.x; sg += gA.x; spp += pA.x*pA.x; spg += pA.x*gA.x; }
        if (a1) { sn += 1.f; sp += pA.y; sg += gA.y; spp += pA.y*pA.y; spg += pA.y*gA.y; }
        if (a2) { sn += 1.f; sp += pA.z; sg += gA.z; spp += pA.z*pA.z; spg += pA.z*gA.z; }
        if (a3) { sn += 1.f; sp += pA.w; sg += gA.w; spp += pA.w*pA.w; spg += pA.w*gA.w; }
        if (b0) { sn += 1.f; sp += pB.x; sg += gB.x; spp += pB.x*pB.x; spg += pB.x*gB.x; }
        if (b1) { sn += 1.f; sp += pB.y; sg += gB.y; spp += pB.y*pB.y; spg += pB.y*gB.y; }
        if (b2) { sn += 1.f; sp += pB.z; sg += gB.z; spp += pB.z*pB.z; spg += pB.z*gB.z; }
        if (b3) { sn += 1.f; sp += pB.w; sg += gB.w; spp += pB.w*pB.w; spg += pB.w*gB.w; }

        unsigned balA0 = __ballot_sync(FULLM, a0);
        unsigned balA1 = __ballot_sync(FULLM, a1);
        unsigned balA2 = __ballot_sync(FULLM, a2);
        unsigned balA3 = __ballot_sync(FULLM, a3);
        unsigned balB0 = __ballot_sync(FULLM, b0);
        unsigned balB1 = __ballot_sync(FULLM, b1);
        unsigned balB2 = __ballot_sync(FULLM, b2);
        unsigned balB3 = __ballot_sync(FULLM, b3);
        int o0 = __popc(balA0);
        int o1 = o0 + __popc(balA1);
        int o2 = o1 + __popc(balA2);
        int o3 = o2 + __popc(balA3);
        int o4 = o3 + __popc(balB0);
        int o5 = o4 + __popc(balB1);
        int o6 = o5 + __popc(balB2);
        int tot = o6 + __popc(balB3);
        int base = 0;
        if (lane == 0 && tot) base = atomicAdd(&s_cnt, tot);
        base = __shfl_sync(FULLM, base, 0);
        if (a0) out[base      + __popc(balA0 & lmask)] = make_float2(pA.x, gA.x);
        if (a1) out[base + o0 + __popc(balA1 & lmask)] = make_float2(pA.y, gA.y);
        if (a2) out[base + o1 + __popc(balA2 & lmask)] = make_float2(pA.z, gA.z);
        if (a3) out[base + o2 + __popc(balA3 & lmask)] = make_float2(pA.w, gA.w);
        if (b0) out[base + o3 + __popc(balB0 & lmask)] = make_float2(pB.x, gB.x);
        if (b1) out[base + o4 + __popc(balB1 & lmask)] = make_float2(pB.y, gB.y);
        if (b2) out[base + o5 + __popc(balB2 & lmask)] = make_float2(pB.z, gB.z);
        if (b3) out[base + o6 + __popc(balB3 & lmask)] = make_float2(pB.w, gB.w);
    }
    for (; i < end; i += TPB) {
        float4 p = __ldcs(&p4[i]);
        float4 g = __ldcs(&g4[i]);
        int4   m = __ldcs(&m4[i]);
        bool v0 = m.x > 0, v1 = m.y > 0, v2 = m.z > 0, v3 = m.w > 0;
        if (v0) { sn += 1.f; sp += p.x; sg += g.x; spp += p.x*p.x; spg += p.x*g.x; }
        if (v1) { sn += 1.f; sp += p.y; sg += g.y; spp += p.y*p.y; spg += p.y*g.y; }
        if (v2) { sn += 1.f; sp += p.z; sg += g.z; spp += p.z*p.z; spg += p.z*g.z; }
        if (v3) { sn += 1.f; sp += p.w; sg += g.w; spp += p.w*p.w; spg += p.w*g.w; }
        unsigned bal0 = __ballot_sync(FULLM, v0);
        unsigned bal1 = __ballot_sync(FULLM, v1);
        unsigned bal2 = __ballot_sync(FULLM, v2);
        unsigned bal3 = __ballot_sync(FULLM, v3);
        int c0   = __popc(bal0);
        int c01  = c0  + __popc(bal1);
        int c012 = c01 + __popc(bal2);
        int tot  = c012 + __popc(bal3);
        int base = 0;
        if (lane == 0 && tot) base = atomicAdd(&s_cnt, tot);
        base = __shfl_sync(FULLM, base, 0);
        if (v0) out[base        + __popc(bal0 & lmask)] = make_float2(p.x, g.x);
        if (v1) out[base + c0   + __popc(bal1 & lmask)] = make_float2(p.y, g.y);
        if (v2) out[base + c01  + __popc(bal2 & lmask)] = make_float2(p.z, g.z);
        if (v3) out[base + c012 + __popc(bal3 & lmask)] = make_float2(p.w, g.w);
    }

    sn = warp_sum(sn); sp = warp_sum(sp); sg = warp_sum(sg);
    spp = warp_sum(spp); spg = warp_sum(spg);
    __shared__ float ws[5][8];
    int w = threadIdx.x >> 5;
    if (lane == 0) { ws[0][w]=sn; ws[1][w]=sp; ws[2][w]=sg; ws[3][w]=spp; ws[4][w]=spg; }
    __syncthreads();
    if (w == 0) {
        float a0 = lane < 8 ? ws[0][lane] : 0.f;
        float a1 = lane < 8 ? ws[1][lane] : 0.f;
        float a2 = lane < 8 ? ws[2][lane] : 0.f;
        float a3 = lane < 8 ? ws[3][lane] : 0.f;
        float a4 = lane < 8 ? ws[4][lane] : 0.f;
        a0 = warp_sum(a0); a1 = warp_sum(a1); a2 = warp_sum(a2);
        a3 = warp_sum(a3); a4 = warp_sum(a4);
        if (lane == 0) {
            g_part[b][blockIdx.x][0] = a0;
            g_part[b][blockIdx.x][1] = a1;
            g_part[b][blockIdx.x][2] = a2;
            g_part[b][blockIdx.x][3] = a3;
            g_part[b][blockIdx.x][4] = a4;
            g_segcnt[b][blockIdx.x] = s_cnt;
        }
    }
}

// ------------------------------ 2. finalize --------------------------------
__global__ void finalize_kernel(float* __restrict__ out0) {
    int b = blockIdx.x;
    int tid = threadIdx.x;
    for (int i = tid; i < HBINS; i += blockDim.x) g_hcnt[b][i] = 0u;
    if (tid == 0) {
        g_candcnt[b] = 0;
        g_sumbelow[b] = 0.0;
        if (b == 0) *out0 = 0.f;
    }
    if (tid < 32) {
        double v0 = (double)g_part[b][tid][0];
        double v1 = (double)g_part[b][tid][1];
        double v2 = (double)g_part[b][tid][2];
        double v3 = (double)g_part[b][tid][3];
        double v4 = (double)g_part[b][tid][4];
        v0 = warp_sum_d(v0); v1 = warp_sum_d(v1); v2 = warp_sum_d(v2);
        v3 = warp_sum_d(v3); v4 = warp_sum_d(v4);
        if (tid == 0) {
            double n  = v0;
            double ns = n < 1.0 ? 1.0 : n;
            double md = v1 / ns, mz = v2 / ns;
            double var = v3 / ns - md * md;
            double cov = v4 / ns - md * mz;
            double alpha = cov / (var + 1e-6);
            double beta  = mz - alpha * md;
            g_alpha[b] = (float)alpha;
            g_beta[b]  = (float)beta;
            int k = (int)floorf(0.8f * (float)n);   // reference-matching f32 arith
            g_k[b] = k;
            g_rank[b] = (long long)k - 1;
        }
    }
}

// ------------------------------ 3. hist ------------------------------------
__global__ __launch_bounds__(TPB) void hist_kernel() {
    int b = blockIdx.y;
    __shared__ unsigned int sh[HBINS];
    for (int i = threadIdx.x; i < HBINS; i += TPB) sh[i] = 0u;
    __syncthreads();

    int cnt = g_segcnt[b][blockIdx.x];
    const float2* in = g_pair + (size_t)b * NMAX + (size_t)blockIdx.x * SEGLEN;
    float a = g_alpha[b], be = g_beta[b];

    int i = threadIdx.x;
    for (; i + 3*TPB < cnt; i += 4*TPB) {
        float2 q0 = in[i];
        float2 q1 = in[i + TPB];
        float2 q2 = in[i + 2*TPB];
        float2 q3 = in[i + 3*TPB];
        float r0 = fabsf(fmaf(a, q0.x, be) - q0.y);
        float r1 = fabsf(fmaf(a, q1.x, be) - q1.y);
        float r2 = fabsf(fmaf(a, q2.x, be) - q2.y);
        float r3 = fabsf(fmaf(a, q3.x, be) - q3.y);
        atomicAdd(&sh[__float_as_uint(r0) >> HSHIFT], 1u);
        atomicAdd(&sh[__float_as_uint(r1) >> HSHIFT], 1u);
        atomicAdd(&sh[__float_as_uint(r2) >> HSHIFT], 1u);
        atomicAdd(&sh[__float_as_uint(r3) >> HSHIFT], 1u);
    }
    for (; i < cnt; i += TPB) {
        float2 pg = in[i];
        float r = fabsf(fmaf(a, pg.x, be) - pg.y);
        atomicAdd(&sh[__float_as_uint(r) >> HSHIFT], 1u);
    }
    __syncthreads();
    for (int j = threadIdx.x; j < HBINS; j += TPB) {
        unsigned c = sh[j];
        if (c) atomicAdd(&g_hcnt[b][j], c);
    }
}

// ---------------------- 4. compact (+level-0 select) -----------------------
__global__ __launch_bounds__(TPB) void compact_kernel() {
    int b = blockIdx.y;
    int tid = threadIdx.x;
    int lane = tid & 31, w = tid >> 5;

    __shared__ unsigned int s_buf[CAP];
    __shared__ int wtot[8];
    __shared__ int s_bin;
    __shared__ long long s_before, s_rankin;
    __shared__ int s_local, s_gbase;

    if (tid == 0) { s_bin = -1; s_local = 0; }
    long long r = g_rank[b];      // k-1; finalize-owned
    __syncthreads();

    // level-0 selection scan over 4096 bins (16 per thread; L2-hot)
    unsigned int c[16];
    int mysum = 0;
    #pragma unroll
    for (int j = 0; j < 16; j++) { c[j] = g_hcnt[b][tid*16+j]; mysum += (int)c[j]; }
    int incl = warp_scan_incl(mysum, lane);
    if (lane == 31) wtot[w] = incl;
    __syncthreads();
    int wbase = 0;
    #pragma unroll
    for (int j = 0; j < 8; j++) wbase += (j < w) ? wtot[j] : 0;
    long long base = (long long)wbase + incl - mysum;
    if (r >= 0 && r >= base && r < base + mysum) {
        long long cum = base;
        #pragma unroll
        for (int j = 0; j < 16; j++) {
            if (r < cum + (long long)c[j]) {
                s_bin = tid*16+j; s_before = cum; s_rankin = r - cum; break;
            }
            cum += (long long)c[j];
        }
    }
    __syncthreads();

    int sel = s_bin;
    if (sel < 0) {                        // k == 0 case
        if (tid == 0 && blockIdx.x == 0) g_sel0[b] = -1;
        return;
    }
    unsigned selu = (unsigned)sel;
    if (tid == 0 && blockIdx.x == 0) {
        g_sel0[b] = sel;
        g_rank2[b] = s_rankin;
        g_cntbelow[b] = s_before;   // exact from scan
    }

    int cnt = g_segcnt[b][blockIdx.x];
    const float2* in = g_pair + (size_t)b * NMAX + (size_t)blockIdx.x * SEGLEN;
    unsigned int* cand = g_cand + (size_t)b * NMAX;
    float a = g_alpha[b], be = g_beta[b];

    float sbelow = 0.f;
    // single sweep in tiles; ILP-8 loads inside each tile; flush on watermark
    for (int t0 = 0; t0 < cnt; t0 += TILE) {
        int tend = t0 + TILE < cnt ? t0 + TILE : cnt;
        int i = t0 + tid;
        for (; i + 7*TPB < tend; i += 8*TPB) {
            float2 q0 = in[i];
            float2 q1 = in[i + TPB];
            float2 q2 = in[i + 2*TPB];
            float2 q3 = in[i + 3*TPB];
            float2 q4 = in[i + 4*TPB];
            float2 q5 = in[i + 5*TPB];
            float2 q6 = in[i + 6*TPB];
            float2 q7 = in[i + 7*TPB];
            float r0 = fabsf(fmaf(a, q0.x, be) - q0.y);
            float r1 = fabsf(fmaf(a, q1.x, be) - q1.y);
            float r2 = fabsf(fmaf(a, q2.x, be) - q2.y);
            float r3 = fabsf(fmaf(a, q3.x, be) - q3.y);
            float r4 = fabsf(fmaf(a, q4.x, be) - q4.y);
            float r5 = fabsf(fmaf(a, q5.x, be) - q5.y);
            float r6 = fabsf(fmaf(a, q6.x, be) - q6.y);
            float r7 = fabsf(fmaf(a, q7.x, be) - q7.y);
            unsigned b0 = __float_as_uint(r0), t0b = b0 >> HSHIFT;
            unsigned b1 = __float_as_uint(r1), t1b = b1 >> HSHIFT;
            unsigned b2 = __float_as_uint(r2), t2b = b2 >> HSHIFT;
            unsigned b3 = __float_as_uint(r3), t3b = b3 >> HSHIFT;
            unsigned b4 = __float_as_uint(r4), t4b = b4 >> HSHIFT;
            unsigned b5 = __float_as_uint(r5), t5b = b5 >> HSHIFT;
            unsigned b6 = __float_as_uint(r6), t6b = b6 >> HSHIFT;
            unsigned b7 = __float_as_uint(r7), t7b = b7 >> HSHIFT;
            if (t0b < selu) sbelow += r0;
            else if (t0b == selu) s_buf[atomicAdd(&s_local, 1)] = b0;
            if (t1b < selu) sbelow += r1;
            else if (t1b == selu) s_buf[atomicAdd(&s_local, 1)] = b1;
            if (t2b < selu) sbelow += r2;
            else if (t2b == selu) s_buf[atomicAdd(&s_local, 1)] = b2;
            if (t3b < selu) sbelow += r3;
            else if (t3b == selu) s_buf[atomicAdd(&s_local, 1)] = b3;
            if (t4b < selu) sbelow += r4;
            else if (t4b == selu) s_buf[atomicAdd(&s_local, 1)] = b4;
            if (t5b < selu) sbelow += r5;
            else if (t5b == selu) s_buf[atomicAdd(&s_local, 1)] = b5;
            if (t6b < selu) sbelow += r6;
            else if (t6b == selu) s_buf[atomicAdd(&s_local, 1)] = b6;
            if (t7b < selu) sbelow += r7;
            else if (t7b == selu) s_buf[atomicAdd(&s_local, 1)] = b7;
        }
        for (; i < tend; i += TPB) {
            float2 pg = in[i];
            float rr = fabsf(fmaf(a, pg.x, be) - pg.y);
            unsigned bits = __float_as_uint(rr);
            unsigned top = bits >> HSHIFT;
            if (top < selu) sbelow += rr;
            else if (top == selu) s_buf[atomicAdd(&s_local, 1)] = bits;
        }
        // flush if next tile could overflow
        if (t0 + TILE < cnt) {
            __syncthreads();
            int nloc = s_local;
            if (nloc + TILE > CAP) {
                if (tid == 0) {
                    s_gbase = atomicAdd(&g_candcnt[b], nloc);
                    s_local = 0;
                }
                __syncthreads();
                int gb = s_gbase;
                for (int j = tid; j < nloc; j += TPB) cand[gb + j] = s_buf[j];
                __syncthreads();
            }
        }
    }
    // final flush
    __syncthreads();
    {
        int nloc = s_local;
        if (nloc > 0) {
            if (tid == 0) s_gbase = atomicAdd(&g_candcnt[b], nloc);
            __syncthreads();
            int gb = s_gbase;
            for (int j = tid; j < nloc; j += TPB) cand[gb + j] = s_buf[j];
        }
    }

    // block-reduce below-bin sum
    float sb = warp_sum(sbelow);
    __shared__ float wsum[8];
    if (lane == 0) wsum[w] = sb;
    __syncthreads();
    if (tid == 0) {
        float tot = 0.f;
        #pragma unroll
        for (int j = 0; j < 8; j++) tot += wsum[j];
        if (tot != 0.f) atomicAdd(&g_sumbelow[b], (double)tot);
    }
}

// ------------------------------ 5. finish ----------------------------------
#define FTPB 1024
__global__ __launch_bounds__(FTPB) void finish_kernel(float* __restrict__ out0) {
    int b = blockIdx.x;
    int tid = threadIdx.x;
    int lane = tid & 31, w = tid >> 5;
    int sel0 = g_sel0[b];
    int k = g_k[b];

    __shared__ unsigned int hist[1024];
    __shared__ int wtot[32];
    __shared__ int s_bin;
    __shared__ long long s_before;
    __shared__ double sred[32];
    __shared__ long long lred[32];

    if (sel0 < 0 || k <= 0) return;   // contributes 0 to the mean

    int m = g_candcnt[b];
    long long rw = g_rank2[b];
    const unsigned int* cand = g_cand + (size_t)b * NMAX;

    // ---- pass A: bits[19:10], 1024 bins (4x unrolled loads for MLP) ----
    hist[tid] = 0u;
    __syncthreads();
    {
        int i = tid;
        for (; i + 3*FTPB < m; i += 4*FTPB) {
            unsigned b0 = cand[i];
            unsigned b1 = cand[i + FTPB];
            unsigned b2 = cand[i + 2*FTPB];
            unsigned b3 = cand[i + 3*FTPB];
            atomicAdd(&hist[(b0 >> 10) & 1023u], 1u);
            atomicAdd(&hist[(b1 >> 10) & 1023u], 1u);
            atomicAdd(&hist[(b2 >> 10) & 1023u], 1u);
            atomicAdd(&hist[(b3 >> 10) & 1023u], 1u);
        }
        for (; i < m; i += FTPB)
            atomicAdd(&hist[(cand[i] >> 10) & 1023u], 1u);
    }
    __syncthreads();
    {
        int mysum = (int)hist[tid];
        int incl = warp_scan_incl(mysum, lane);
        if (lane == 31) wtot[w] = incl;
        __syncthreads();
        int wbase = 0;
        for (int j = 0; j < w; j++) wbase += wtot[j];
        long long base = (long long)wbase + incl - mysum;
        if (rw >= base && rw < base + mysum) { s_bin = tid; s_before = base; }
        __syncthreads();
    }
    int selA = s_bin;
    rw -= s_before;
    __syncthreads();

    // ---- pass B: bits[9:0], 1024 bins (4x unrolled) ----
    hist[tid] = 0u;
    __syncthreads();
    {
        unsigned selAu = (unsigned)selA;
        int i = tid;
        for (; i + 3*FTPB < m; i += 4*FTPB) {
            unsigned b0 = cand[i];
            unsigned b1 = cand[i + FTPB];
            unsigned b2 = cand[i + 2*FTPB];
            unsigned b3 = cand[i + 3*FTPB];
            if (((b0 >> 10) & 1023u) == selAu) atomicAdd(&hist[b0 & 1023u], 1u);
            if (((b1 >> 10) & 1023u) == selAu) atomicAdd(&hist[b1 & 1023u], 1u);
            if (((b2 >> 10) & 1023u) == selAu) atomicAdd(&hist[b2 & 1023u], 1u);
            if (((b3 >> 10) & 1023u) == selAu) atomicAdd(&hist[b3 & 1023u], 1u);
        }
        for (; i < m; i += FTPB) {
            unsigned bits = cand[i];
            if (((bits >> 10) & 1023u) == selAu)
                atomicAdd(&hist[bits & 1023u], 1u);
        }
    }
    __syncthreads();
    {
        int mysum = (int)hist[tid];
        int incl = warp_scan_incl(mysum, lane);
        if (lane == 31) wtot[w] = incl;
        __syncthreads();
        int wbase = 0;
        for (int j = 0; j < w; j++) wbase += wtot[j];
        long long base = (long long)wbase + incl - mysum;
        if (rw >= base && rw < base + mysum) s_bin = tid;
        __syncthreads();
    }
    int selB = s_bin;
    unsigned v_bits = ((unsigned)sel0 << HSHIFT) | ((unsigned)selA << 10) | (unsigned)selB;
    float v = __uint_as_float(v_bits);

    // ---- pass C: sum/count of candidates strictly below v (4x unrolled) ----
    double s = 0.0;
    long long c = 0;
    {
        int i = tid;
        for (; i + 3*FTPB < m; i += 4*FTPB) {
            unsigned b0 = cand[i];
            unsigned b1 = cand[i + FTPB];
            unsigned b2 = cand[i + 2*FTPB];
            unsigned b3 = cand[i + 3*FTPB];
            if (b0 < v_bits) { s += (double)__uint_as_float(b0); c++; }
            if (b1 < v_bits) { s += (double)__uint_as_float(b1); c++; }
            if (b2 < v_bits) { s += (double)__uint_as_float(b2); c++; }
            if (b3 < v_bits) { s += (double)__uint_as_float(b3); c++; }
        }
        for (; i < m; i += FTPB) {
            unsigned bits = cand[i];
            if (bits < v_bits) { s += (double)__uint_as_float(bits); c++; }
        }
    }
    s = warp_sum_d(s);
    c = warp_sum_ll(c);
    if (lane == 0) { sred[w] = s; lred[w] = c; }
    __syncthreads();
    if (w == 0) {
        double sv = sred[lane];
        long long cv = lred[lane];
        sv = warp_sum_d(sv);
        cv = warp_sum_ll(cv);
        if (lane == 0) {
            long long total_less = g_cntbelow[b] + cv;
            double kept = g_sumbelow[b] + sv +
                          (double)((long long)k - total_less) * (double)v;
            float loss = (float)(kept / (double)k);
            atomicAdd(out0, loss / (float)BB);
        }
    }
}

// ------------------------------ launch -------------------------------------
extern "C" void kernel_launch(void* const* d_in, const int* in_sizes, int n_in,
                              void* d_out, int out_size) {
    const float* pred = (const float*)d_in[0];
    const float* gt   = (const float*)d_in[1];
    const int*   mask = (const int*)d_in[2];
    float* out = (float*)d_out;

    int total = in_sizes[0];
    int N = total / BB;

    dim3 grid(BLKX, BB);

    pack_kernel<<<grid, TPB>>>(pred, gt, mask, N);
    finalize_kernel<<<BB, TPB>>>(out);
    hist_kernel<<<grid, TPB>>>();
    compact_kernel<<<grid, TPB>>>();
    finish_kernel<<<BB, FTPB>>>(out);
}